// round 17
// baseline (speedup 1.0000x reference)
#include <cuda_runtime.h>
#include <cstdint>
#include <float.h>

#define MAXVAL   5843
#define BATCH    4
#define NROWS    (BATCH * MAXVAL)     // 23372
#define TOP_K    200
#define STEP     30
#define NSTEPS   189
#define OUT_ELEMS ((size_t)NROWS * MAXVAL)   // 136,562,596 floats

#define MS_THREADS 256
#define MS_BLOCKS  8192

#define WPT        7                  // 7*32 >= 200
#define WARPS_PB   8
#define BD_THREADS (WARPS_PB * 32)
#define BD_BLOCKS  ((NROWS + WARPS_PB - 1) / WARPS_PB)   // 2922

// ───────────────────────── kernel 1: pure linear zero stream ─────────────────────────
// No per-row logic, no reads, no barriers: the cleanest possible write pattern.
__global__ __launch_bounds__(MS_THREADS)
void zero_all_kernel(float* __restrict__ out) {
    // 16B-align the bulk region (cudaMalloc base is 256B-aligned, but be safe).
    const uintptr_t base = (uintptr_t)out;
    const int head = (int)(((16u - (base & 15u)) & 15u) >> 2);   // 0..3

    const size_t tid = (size_t)blockIdx.x * MS_THREADS + threadIdx.x;

    if (tid < (size_t)head) out[tid] = 0.0f;

    const size_t nvec = (OUT_ELEMS - head) >> 2;
    float4* __restrict__ p = (float4*)(out + head);
    const float4 z = make_float4(0.0f, 0.0f, 0.0f, 0.0f);
    const size_t stride = (size_t)MS_BLOCKS * MS_THREADS;
    for (size_t k = tid; k < nvec; k += stride)
        __stcs(&p[k], z);

    const size_t tail_lo = (size_t)head + (nvec << 2);
    const size_t tail_n  = OUT_ELEMS - tail_lo;
    if (tid < tail_n) out[tail_lo + tid] = 0.0f;
}

// ───────────────────────── kernel 2: band softmax (warp-per-row) ─────────────────────
__inline__ __device__ float warp_max(float v) {
    #pragma unroll
    for (int o = 16; o > 0; o >>= 1)
        v = fmaxf(v, __shfl_xor_sync(0xFFFFFFFFu, v, o));
    return v;
}
__inline__ __device__ float warp_sum(float v) {
    #pragma unroll
    for (int o = 16; o > 0; o >>= 1)
        v += __shfl_xor_sync(0xFFFFFFFFu, v, o);
    return v;
}

__global__ __launch_bounds__(BD_THREADS)
void band_kernel(const float* __restrict__ X, float* __restrict__ out) {
    const int lane = threadIdx.x & 31;
    const int row  = blockIdx.x * WARPS_PB + (threadIdx.x >> 5);
    if (row >= NROWS) return;

    const int s = min(row % MAXVAL, NSTEPS - 1) * STEP;   // window start (<= 5640)
    const float* __restrict__ xw = X + (size_t)row * MAXVAL + s;

    float v[WPT];
    #pragma unroll
    for (int k = 0; k < WPT; k++) {
        const int idx = lane + (k << 5);
        v[k] = (idx < TOP_K) ? __ldg(xw + idx) : -FLT_MAX;
    }

    float m = v[0];
    #pragma unroll
    for (int k = 1; k < WPT; k++) m = fmaxf(m, v[k]);
    m = warp_max(m);

    float e[WPT];
    float acc = 0.0f;
    #pragma unroll
    for (int k = 0; k < WPT; k++) {
        const int idx = lane + (k << 5);
        e[k] = (idx < TOP_K) ? __expf(v[k] - m) : 0.0f;
        acc += e[k];
    }
    acc = warp_sum(acc);
    const float inv = __frcp_rn(acc);

    float* __restrict__ ob = out + (size_t)row * MAXVAL + s;
    #pragma unroll
    for (int k = 0; k < WPT; k++) {
        const int idx = lane + (k << 5);
        if (idx < TOP_K) ob[idx] = e[k] * inv;
    }
}

extern "C" void kernel_launch(void* const* d_in, const int* in_sizes, int n_in,
                              void* d_out, int out_size) {
    const float* X = (const float*)d_in[0];
    float* out = (float*)d_out;
    (void)in_sizes; (void)n_in; (void)out_size;
    // Stream-ordered: bands overwrite their freshly-zeroed 800B windows.
    zero_all_kernel<<<MS_BLOCKS, MS_THREADS>>>(out);
    band_kernel<<<BD_BLOCKS, BD_THREADS>>>(X, out);
}